// round 16
// baseline (speedup 1.0000x reference)
#include <cuda_runtime.h>
#include <cuda_fp16.h>
#include <cstdint>

#define GMM_M  64
#define GMM_D  16
#define TPB    128
#define PPB    128
#define PF1    72               // stage-1 K pitch in halves (144 B, conflict-free)
#define PF1B   144
#define PF2    72               // stage-2 K pitch
#define PF2B   144

// static SMEM layout (31360 B)
#define OFF_W1 0                                  // [64][PF1]  = 9216 B
#define OFF_W2 9216                               // [24][PF2]  = 3456 B
#define OFF_C  12672                              // f32[64]    = 256 B
#define OFF_F  12928                              // [128][PF1] = 18432 B
#define OFF_STG OFF_F                             // f32[128*17] overlays F
#define SMEM_SZ 31360

#define LOG2E  1.4426950408889634f
#define LN2F   0.6931471805599453f

__device__ __align__(16) __half g_W1h[GMM_M * PF1];
__device__ __align__(16) __half g_W2h[24 * PF2];
__device__ float    g_Cf[GMM_M];
__device__ float    g_part[8192];
__device__ unsigned g_count = 0;

// ---------------- helpers ----------------
__device__ __forceinline__ uint32_t smem_u32(const void* p) {
    uint32_t a;
    asm("{ .reg .u64 t; cvta.to.shared.u64 t, %1; cvt.u32.u64 %0, t; }" : "=r"(a) : "l"(p));
    return a;
}
__device__ __forceinline__ float ex2f(float x) {
    float r; asm("ex2.approx.f32 %0, %1;" : "=f"(r) : "f"(x)); return r;
}
__device__ __forceinline__ uint32_t h2u(__half2 h) { return *reinterpret_cast<uint32_t*>(&h); }

__device__ __forceinline__ void ldsm4(uint32_t* r, uint32_t addr) {
    asm volatile("ldmatrix.sync.aligned.m8n8.x4.shared.b16 {%0,%1,%2,%3}, [%4];"
        : "=r"(r[0]), "=r"(r[1]), "=r"(r[2]), "=r"(r[3]) : "r"(addr));
}
__device__ __forceinline__ void ldsm2(uint32_t* r, uint32_t addr) {
    asm volatile("ldmatrix.sync.aligned.m8n8.x2.shared.b16 {%0,%1}, [%2];"
        : "=r"(r[0]), "=r"(r[1]) : "r"(addr));
}
__device__ __forceinline__ void mma16816(float* d, const uint32_t* a, const uint32_t* b) {
    asm volatile("mma.sync.aligned.m16n8k16.row.col.f32.f16.f16.f32 "
        "{%0,%1,%2,%3}, {%4,%5,%6,%7}, {%8,%9}, {%0,%1,%2,%3};"
        : "+f"(d[0]), "+f"(d[1]), "+f"(d[2]), "+f"(d[3])
        : "r"(a[0]), "r"(a[1]), "r"(a[2]), "r"(a[3]), "r"(b[0]), "r"(b[1]));
}

// ---------------- kernel 1: build fp16 W images + f32 C ----------------
__global__ void __launch_bounds__(1024)
gmm_precompute(const float* __restrict__ wghts,
               const float* __restrict__ means,
               const float* __restrict__ dcovs) {
    const int tid = threadIdx.x;
    const __half hz = __float2half_rn(0.0f);
    for (int i = tid; i < GMM_M * PF1; i += 1024) g_W1h[i] = hz;
    for (int i = tid; i < 24 * PF2; i += 1024)    g_W2h[i] = hz;
    __syncthreads();

    const int m = tid >> 4;
    const int d = tid & 15;

    const float dc   = dcovs[m * GMM_D + d];
    const float mu   = means[m * GMM_D + d];
    const float prec = 1.0f / dc;
    const float A = -0.5f * prec * LOG2E;
    const float B = prec * mu * LOG2E;

    float cpart = (-0.5f * prec * mu * mu - 0.5f * __logf(dc)) * LOG2E;
    #pragma unroll
    for (int o = 8; o > 0; o >>= 1)
        cpart += __shfl_down_sync(0xffffffffu, cpart, o, 16);

    const __half Ah = __float2half_rn(A);
    const __half Bh = __float2half_rn(B);

    __half* w1 = g_W1h + m * PF1;
    w1[d]      = Ah;
    w1[16 + d] = Bh;
    w1[32 + d] = __float2half_rn(A - __half2float(Ah));
    w1[48 + d] = __float2half_rn(B - __half2float(Bh));

    if (d == 0)
        g_Cf[m] = cpart + (__logf(wghts[m]) - 8.0f * __logf(6.283185307f)) * LOG2E;

    g_W2h[d * PF2 + m] = __float2half_rn(mu);
    if (tid < GMM_M) g_W2h[16 * PF2 + tid] = __float2half_rn(1.0f);   // likes row
}

// ---------------- kernel 2: fp16 mma.sync GMM E-step (mt-split) ----------------
__global__ void __launch_bounds__(TPB, 6)
gmm_main(const float* __restrict__ data,
         float* __restrict__ out,
         int T, float invT) {
    __shared__ __align__(16) char dsm[SMEM_SZ];
    __shared__ float sRed[TPB];
    __shared__ bool  sLast;

    const int tid  = threadIdx.x;
    const int lane = tid & 31;
    const int wid  = tid >> 5;
    const uint32_t sb = smem_u32(dsm);

    // copy W images + C into SMEM
    {
        const float4* s1 = (const float4*)g_W1h;
        float4*       d1 = (float4*)(dsm + OFF_W1);
        for (int i = tid; i < (GMM_M * PF1 * 2) / 16; i += TPB) d1[i] = s1[i];
        const float4* s2 = (const float4*)g_W2h;
        float4*       d2 = (float4*)(dsm + OFF_W2);
        for (int i = tid; i < (24 * PF2 * 2) / 16; i += TPB) d2[i] = s2[i];
        if (tid < GMM_M) ((float*)(dsm + OFF_C))[tid] = g_Cf[tid];
    }

    // features -> F row: k0-15 x2_h | k16-31 x_h | k32-47 x2_l | k48-63 x_l
    const int  base  = blockIdx.x * PPB;
    const int  tglob = base + tid;
    const bool valid = (tglob < T);
    {
        float xv[GMM_D];
        if (valid) {
            const float4* dp = (const float4*)(data + (size_t)tglob * GMM_D);
            #pragma unroll
            for (int q = 0; q < 4; q++) {
                const float4 f = dp[q];
                xv[4*q] = f.x; xv[4*q+1] = f.y; xv[4*q+2] = f.z; xv[4*q+3] = f.w;
            }
        } else {
            #pragma unroll
            for (int d = 0; d < GMM_D; d++) xv[d] = 0.0f;
        }
        uint32_t row[PF1 / 2];
        #pragma unroll
        for (int j = 0; j < PF1 / 2; j++) row[j] = 0u;
        #pragma unroll
        for (int q = 0; q < 8; q++) {
            const float u0 = xv[2*q] * xv[2*q], u1 = xv[2*q+1] * xv[2*q+1];
            const __half2 uh2 = __floats2half2_rn(u0, u1);
            const __half2 vh2 = __floats2half2_rn(xv[2*q], xv[2*q+1]);
            row[q]      = h2u(uh2);
            row[8 + q]  = h2u(vh2);
            row[16 + q] = h2u(__floats2half2_rn(u0 - __low2float(uh2), u1 - __high2float(uh2)));
            row[24 + q] = h2u(__floats2half2_rn(xv[2*q] - __low2float(vh2),
                                                xv[2*q+1] - __high2float(vh2)));
        }
        uint4* fr = (uint4*)(dsm + OFF_F + tid * PF1B);
        #pragma unroll
        for (int q = 0; q < 9; q++)
            fr[q] = make_uint4(row[4*q], row[4*q+1], row[4*q+2], row[4*q+3]);
    }
    __syncthreads();

    const uint32_t fb  = sb + OFF_F;
    const uint32_t w1b = sb + OFF_W1;
    const uint32_t w2b = sb + OFF_W2;
    const int rselA = lane & 15;
    const uint32_t koffA = (lane >> 4) * 16;
    const int nrowB = (lane & 7) + ((lane & 16) ? 8 : 0);
    const uint32_t koffB = (lane & 8) ? 16u : 0u;
    const int g = lane >> 2, t = lane & 3;

    float sv[2][8];       // carried posterior-scaled outputs per mt-tile
    float llsum = 0.0f;

    #pragma unroll
    for (int mt = 0; mt < 2; mt++) {
        // ---- stage 1: E = fh*Wh + fh*Wl + fl*Wh ----
        float acc[8][4];
        #pragma unroll
        for (int nt = 0; nt < 8; nt++)
            #pragma unroll
            for (int i = 0; i < 4; i++) acc[nt][i] = 0.0f;

        #pragma unroll
        for (int ks = 0; ks < 2; ks++) {
            uint32_t a1[4], a2[4];
            const uint32_t ra = fb + (wid * 32 + mt * 16 + rselA) * PF1B + ks * 32 + koffA;
            ldsm4(a1, ra);
            ldsm4(a2, ra + 64);

            uint32_t bh[8][2], bl[8][2];
            #pragma unroll
            for (int p = 0; p < 4; p++) {
                const uint32_t rb = w1b + (p * 16 + nrowB) * PF1B + ks * 32 + koffB;
                uint32_t r[4];
                ldsm4(r, rb);
                bh[2*p][0] = r[0]; bh[2*p][1] = r[1];
                bh[2*p+1][0] = r[2]; bh[2*p+1][1] = r[3];
                ldsm4(r, rb + 64);
                bl[2*p][0] = r[0]; bl[2*p][1] = r[1];
                bl[2*p+1][0] = r[2]; bl[2*p+1][1] = r[3];
            }
            #pragma unroll
            for (int nt = 0; nt < 8; nt++) {
                mma16816(acc[nt], a1, bh[nt]);
                mma16816(acc[nt], a1, bl[nt]);
                mma16816(acc[nt], a2, bh[nt]);
            }
        }

        // exact f32 C per mixture
        {
            const float* sC = (const float*)(dsm + OFF_C);
            #pragma unroll
            for (int nt = 0; nt < 8; nt++) {
                const float c0 = sC[nt * 8 + 2 * t];
                const float c1 = sC[nt * 8 + 2 * t + 1];
                acc[nt][0] += c0; acc[nt][1] += c1;
                acc[nt][2] += c0; acc[nt][3] += c1;
            }
        }

        // ---- row-max, exp2, pack p' ----
        float mg = -1e30f, mg8 = -1e30f;
        #pragma unroll
        for (int nt = 0; nt < 8; nt++) {
            mg  = fmaxf(mg,  fmaxf(acc[nt][0], acc[nt][1]));
            mg8 = fmaxf(mg8, fmaxf(acc[nt][2], acc[nt][3]));
        }
        mg  = fmaxf(mg,  __shfl_xor_sync(0xffffffffu, mg, 1));
        mg  = fmaxf(mg,  __shfl_xor_sync(0xffffffffu, mg, 2));
        mg8 = fmaxf(mg8, __shfl_xor_sync(0xffffffffu, mg8, 1));
        mg8 = fmaxf(mg8, __shfl_xor_sync(0xffffffffu, mg8, 2));

        uint32_t pH[8][2];
        #pragma unroll
        for (int nt = 0; nt < 8; nt++) {
            const float p0 = ex2f(acc[nt][0] - mg);
            const float p1 = ex2f(acc[nt][1] - mg);
            const float p2 = ex2f(acc[nt][2] - mg8);
            const float p3 = ex2f(acc[nt][3] - mg8);
            pH[nt][0] = h2u(__floats2half2_rn(p0, p1));
            pH[nt][1] = h2u(__floats2half2_rn(p2, p3));
        }

        // ---- stage 2: [num | like] = P' * W2^T ----
        float acc2[3][4];
        #pragma unroll
        for (int nt = 0; nt < 3; nt++)
            #pragma unroll
            for (int i = 0; i < 4; i++) acc2[nt][i] = 0.0f;

        #pragma unroll
        for (int ks2 = 0; ks2 < 4; ks2++) {
            uint32_t bW2[3][2];
            {
                uint32_t r[4];
                ldsm4(r, w2b + nrowB * PF2B + ks2 * 32 + koffB);
                bW2[0][0] = r[0]; bW2[0][1] = r[1];
                bW2[1][0] = r[2]; bW2[1][1] = r[3];
                uint32_t r2[2];
                ldsm2(r2, w2b + (16 + (lane & 7)) * PF2B + ks2 * 32 + koffB);
                bW2[2][0] = r2[0]; bW2[2][1] = r2[1];
            }
            const int nt2 = 2 * ks2;
            uint32_t a2[4];
            a2[0] = pH[nt2][0];   a2[1] = pH[nt2][1];
            a2[2] = pH[nt2+1][0]; a2[3] = pH[nt2+1][1];
            #pragma unroll
            for (int nt = 0; nt < 3; nt++)
                mma16816(acc2[nt], a2, bW2[nt]);
        }

        // ---- posterior scaling (carried in registers) ----
        const float likeg  = __shfl_sync(0xffffffffu, acc2[2][0], lane & ~3);
        const float likeg8 = __shfl_sync(0xffffffffu, acc2[2][2], lane & ~3);
        const float invg  = __fdividef(1.0f, likeg);
        const float invg8 = __fdividef(1.0f, likeg8);
        sv[mt][0] = acc2[0][0] * invg;   sv[mt][1] = acc2[0][1] * invg;
        sv[mt][2] = acc2[1][0] * invg;   sv[mt][3] = acc2[1][1] * invg;
        sv[mt][4] = acc2[0][2] * invg8;  sv[mt][5] = acc2[0][3] * invg8;
        sv[mt][6] = acc2[1][2] * invg8;  sv[mt][7] = acc2[1][3] * invg8;
        if (t == 0) {
            const int r = wid * 32 + mt * 16 + g;
            if (base + r < T)     llsum += __logf(likeg)  + mg  * LN2F;
            if (base + r + 8 < T) llsum += __logf(likeg8) + mg8 * LN2F;
        }
    }

    // ---- epilogue: transpose-stage (overlays F after all reads done) ----
    __syncthreads();
    float* stg = (float*)(dsm + OFF_STG);
    #pragma unroll
    for (int mt = 0; mt < 2; mt++) {
        const int r = wid * 32 + mt * 16 + g;
        stg[r * 17 + 2*t]         = sv[mt][0];
        stg[r * 17 + 2*t + 1]     = sv[mt][1];
        stg[r * 17 + 8 + 2*t]     = sv[mt][2];
        stg[r * 17 + 9 + 2*t]     = sv[mt][3];
        stg[(r+8) * 17 + 2*t]     = sv[mt][4];
        stg[(r+8) * 17 + 2*t + 1] = sv[mt][5];
        stg[(r+8) * 17 + 8 + 2*t] = sv[mt][6];
        stg[(r+8) * 17 + 9 + 2*t] = sv[mt][7];
    }
    __syncthreads();
    {
        float* op = out + 1 + (size_t)base * GMM_D;
        const int limit = min(PPB, T - base) * GMM_D;
        for (int i = tid; i < limit; i += TPB)
            op[i] = stg[(i >> 4) * 17 + (i & 15)];
    }

    // deterministic block reduction + fused finalize
    sRed[tid] = llsum;
    __syncthreads();
    #pragma unroll
    for (int s = TPB / 2; s > 0; s >>= 1) {
        if (tid < s) sRed[tid] += sRed[tid + s];
        __syncthreads();
    }
    if (tid == 0) {
        g_part[blockIdx.x] = sRed[0];
        __threadfence();
        unsigned old = atomicAdd(&g_count, 1u);
        sLast = (old == (unsigned)(gridDim.x - 1));
    }
    __syncthreads();
    if (sLast) {
        __threadfence();
        float acc3 = 0.0f;
        for (int i = tid; i < (int)gridDim.x; i += TPB) acc3 += g_part[i];
        sRed[tid] = acc3;
        __syncthreads();
        #pragma unroll
        for (int s = TPB / 2; s > 0; s >>= 1) {
            if (tid < s) sRed[tid] += sRed[tid + s];
            __syncthreads();
        }
        if (tid == 0) {
            out[0] = sRed[0] * invT;
            g_count = 0;
        }
    }
}

extern "C" void kernel_launch(void* const* d_in, const int* in_sizes, int n_in,
                              void* d_out, int out_size) {
    const float* data  = (const float*)d_in[0];
    const float* wghts = (const float*)d_in[1];
    const float* means = (const float*)d_in[2];
    const float* dcovs = (const float*)d_in[3];
    float* out = (float*)d_out;

    const int T = in_sizes[0] / GMM_D;
    const int grid = (T + PPB - 1) / PPB;

    gmm_precompute<<<1, 1024>>>(wghts, means, dcovs);
    gmm_main<<<grid, TPB>>>(data, out, T, 1.0f / (float)T);
}

// round 17
// speedup vs baseline: 1.0707x; 1.0707x over previous
#include <cuda_runtime.h>
#include <cuda_fp16.h>
#include <cstdint>

#define GMM_M  64
#define GMM_D  16
#define TPB    128
#define PPB    256              // 2 points per thread
#define PF1    72               // stage-1 K pitch in halves (144 B, conflict-free)
#define PF1B   144
#define PF1F   36               // pitch in floats
#define PF2    72
#define PF2B   144

// dynamic SMEM layout (49792 B)
#define OFF_W1 0                                  // [64][PF1]   = 9216 B
#define OFF_W2 9216                               // [24][PF2]   = 3456 B
#define OFF_C  12672                              // f32[64]     = 256 B
#define OFF_F  12928                              // [256][PF1]  = 36864 B (staging overlays per-warp)
#define DSMEM  49792

#define LOG2E  1.4426950408889634f
#define LN2F   0.6931471805599453f

__device__ __align__(16) __half g_W1h[GMM_M * PF1];
__device__ __align__(16) __half g_W2h[24 * PF2];
__device__ float    g_Cf[GMM_M];
__device__ float    g_part[8192];
__device__ unsigned g_count = 0;

// ---------------- helpers ----------------
__device__ __forceinline__ uint32_t smem_u32(const void* p) {
    uint32_t a;
    asm("{ .reg .u64 t; cvta.to.shared.u64 t, %1; cvt.u32.u64 %0, t; }" : "=r"(a) : "l"(p));
    return a;
}
__device__ __forceinline__ float ex2f(float x) {
    float r; asm("ex2.approx.f32 %0, %1;" : "=f"(r) : "f"(x)); return r;
}
__device__ __forceinline__ uint32_t h2u(__half2 h) { return *reinterpret_cast<uint32_t*>(&h); }

__device__ __forceinline__ void ldsm4(uint32_t* r, uint32_t addr) {
    asm volatile("ldmatrix.sync.aligned.m8n8.x4.shared.b16 {%0,%1,%2,%3}, [%4];"
        : "=r"(r[0]), "=r"(r[1]), "=r"(r[2]), "=r"(r[3]) : "r"(addr));
}
__device__ __forceinline__ void ldsm2(uint32_t* r, uint32_t addr) {
    asm volatile("ldmatrix.sync.aligned.m8n8.x2.shared.b16 {%0,%1}, [%2];"
        : "=r"(r[0]), "=r"(r[1]) : "r"(addr));
}
__device__ __forceinline__ void mma16816(float* d, const uint32_t* a, const uint32_t* b) {
    asm volatile("mma.sync.aligned.m16n8k16.row.col.f32.f16.f16.f32 "
        "{%0,%1,%2,%3}, {%4,%5,%6,%7}, {%8,%9}, {%0,%1,%2,%3};"
        : "+f"(d[0]), "+f"(d[1]), "+f"(d[2]), "+f"(d[3])
        : "r"(a[0]), "r"(a[1]), "r"(a[2]), "r"(a[3]), "r"(b[0]), "r"(b[1]));
}

// ---------------- kernel 1: build fp16 W images + f32 C ----------------
__global__ void __launch_bounds__(1024)
gmm_precompute(const float* __restrict__ wghts,
               const float* __restrict__ means,
               const float* __restrict__ dcovs) {
    const int tid = threadIdx.x;
    const __half hz = __float2half_rn(0.0f);
    for (int i = tid; i < GMM_M * PF1; i += 1024) g_W1h[i] = hz;
    for (int i = tid; i < 24 * PF2; i += 1024)    g_W2h[i] = hz;
    __syncthreads();

    const int m = tid >> 4;
    const int d = tid & 15;

    const float dc   = dcovs[m * GMM_D + d];
    const float mu   = means[m * GMM_D + d];
    const float prec = 1.0f / dc;
    const float A = -0.5f * prec * LOG2E;
    const float B = prec * mu * LOG2E;

    float cpart = (-0.5f * prec * mu * mu - 0.5f * __logf(dc)) * LOG2E;
    #pragma unroll
    for (int o = 8; o > 0; o >>= 1)
        cpart += __shfl_down_sync(0xffffffffu, cpart, o, 16);

    const __half Ah = __float2half_rn(A);
    const __half Bh = __float2half_rn(B);

    __half* w1 = g_W1h + m * PF1;
    w1[d]      = Ah;
    w1[16 + d] = Bh;
    w1[32 + d] = __float2half_rn(A - __half2float(Ah));
    w1[48 + d] = __float2half_rn(B - __half2float(Bh));

    if (d == 0)
        g_Cf[m] = cpart + (__logf(wghts[m]) - 8.0f * __logf(6.283185307f)) * LOG2E;

    g_W2h[d * PF2 + m] = __float2half_rn(mu);
    if (tid < GMM_M) g_W2h[16 * PF2 + tid] = __float2half_rn(1.0f);   // likes row
}

// ---------------- kernel 2: fp16 mma.sync GMM E-step (PPB=256, paired tiles) ----------------
__global__ void __launch_bounds__(TPB, 4)
gmm_main(const float* __restrict__ data,
         float* __restrict__ out,
         int T, float invT) {
    extern __shared__ __align__(16) char dsm[];
    __shared__ float sRed[TPB];
    __shared__ bool  sLast;

    const int tid  = threadIdx.x;
    const int lane = tid & 31;
    const int wid  = tid >> 5;
    const uint32_t sb = smem_u32(dsm);

    // copy W images + C into SMEM
    {
        const float4* s1 = (const float4*)g_W1h;
        float4*       d1 = (float4*)(dsm + OFF_W1);
        for (int i = tid; i < (GMM_M * PF1 * 2) / 16; i += TPB) d1[i] = s1[i];
        const float4* s2 = (const float4*)g_W2h;
        float4*       d2 = (float4*)(dsm + OFF_W2);
        for (int i = tid; i < (24 * PF2 * 2) / 16; i += TPB) d2[i] = s2[i];
        if (tid < GMM_M) ((float*)(dsm + OFF_C))[tid] = g_Cf[tid];
    }

    // features -> F rows (2 points per thread): k0-15 x2_h | k16-31 x_h | k32-47 x2_l | k48-63 x_l
    const int base = blockIdx.x * PPB;
    #pragma unroll
    for (int j = 0; j < 2; j++) {
        const int  prow  = tid + j * TPB;
        const int  tglob = base + prow;
        const bool vld   = (tglob < T);
        float xv[GMM_D];
        if (vld) {
            const float4* dp = (const float4*)(data + (size_t)tglob * GMM_D);
            #pragma unroll
            for (int q = 0; q < 4; q++) {
                const float4 f = dp[q];
                xv[4*q] = f.x; xv[4*q+1] = f.y; xv[4*q+2] = f.z; xv[4*q+3] = f.w;
            }
        } else {
            #pragma unroll
            for (int d = 0; d < GMM_D; d++) xv[d] = 0.0f;
        }
        uint32_t row[PF1 / 2];
        #pragma unroll
        for (int jj = 0; jj < PF1 / 2; jj++) row[jj] = 0u;
        #pragma unroll
        for (int q = 0; q < 8; q++) {
            const float u0 = xv[2*q] * xv[2*q], u1 = xv[2*q+1] * xv[2*q+1];
            const __half2 uh2 = __floats2half2_rn(u0, u1);
            const __half2 vh2 = __floats2half2_rn(xv[2*q], xv[2*q+1]);
            row[q]      = h2u(uh2);
            row[8 + q]  = h2u(vh2);
            row[16 + q] = h2u(__floats2half2_rn(u0 - __low2float(uh2), u1 - __high2float(uh2)));
            row[24 + q] = h2u(__floats2half2_rn(xv[2*q] - __low2float(vh2),
                                                xv[2*q+1] - __high2float(vh2)));
        }
        uint4* fr = (uint4*)(dsm + OFF_F + prow * PF1B);
        #pragma unroll
        for (int q = 0; q < 9; q++)
            fr[q] = make_uint4(row[4*q], row[4*q+1], row[4*q+2], row[4*q+3]);
    }
    __syncthreads();

    const uint32_t fb  = sb + OFF_F;
    const uint32_t w1b = sb + OFF_W1;
    const uint32_t w2b = sb + OFF_W2;
    const int rselA = lane & 15;
    const uint32_t koffA = (lane >> 4) * 16;
    const int nrowB = (lane & 7) + ((lane & 16) ? 8 : 0);
    const uint32_t koffB = (lane & 8) ? 16u : 0u;
    const int g = lane >> 2, t = lane & 3;
    float* fstg = (float*)(dsm + OFF_F);

    float llsum = 0.0f;

    // warp wid owns point rows [wid*64, wid*64+64): 2 pairs of 2 tiles
    #pragma unroll
    for (int pp = 0; pp < 2; pp++) {
        const int rowbase = wid * 64 + pp * 32;

        // ---- stage 1 (paired tiles share B fragments) ----
        float acc[2][8][4];
        #pragma unroll
        for (int mt = 0; mt < 2; mt++)
            #pragma unroll
            for (int nt = 0; nt < 8; nt++)
                #pragma unroll
                for (int i = 0; i < 4; i++) acc[mt][nt][i] = 0.0f;

        #pragma unroll
        for (int ks = 0; ks < 2; ks++) {
            uint32_t a1[2][4], a2[2][4];
            #pragma unroll
            for (int mt = 0; mt < 2; mt++) {
                const uint32_t ra = fb + (rowbase + mt * 16 + rselA) * PF1B + ks * 32 + koffA;
                ldsm4(a1[mt], ra);
                ldsm4(a2[mt], ra + 64);
            }
            uint32_t bh[8][2], bl[8][2];
            #pragma unroll
            for (int p = 0; p < 4; p++) {
                const uint32_t rb = w1b + (p * 16 + nrowB) * PF1B + ks * 32 + koffB;
                uint32_t r[4];
                ldsm4(r, rb);
                bh[2*p][0] = r[0]; bh[2*p][1] = r[1];
                bh[2*p+1][0] = r[2]; bh[2*p+1][1] = r[3];
                ldsm4(r, rb + 64);
                bl[2*p][0] = r[0]; bl[2*p][1] = r[1];
                bl[2*p+1][0] = r[2]; bl[2*p+1][1] = r[3];
            }
            #pragma unroll
            for (int nt = 0; nt < 8; nt++)
                #pragma unroll
                for (int mt = 0; mt < 2; mt++) {
                    mma16816(acc[mt][nt], a1[mt], bh[nt]);
                    mma16816(acc[mt][nt], a1[mt], bl[nt]);
                    mma16816(acc[mt][nt], a2[mt], bh[nt]);
                }
        }

        // exact f32 C
        {
            const float* sC = (const float*)(dsm + OFF_C);
            #pragma unroll
            for (int nt = 0; nt < 8; nt++) {
                const float c0 = sC[nt * 8 + 2 * t];
                const float c1 = sC[nt * 8 + 2 * t + 1];
                #pragma unroll
                for (int mt = 0; mt < 2; mt++) {
                    acc[mt][nt][0] += c0; acc[mt][nt][1] += c1;
                    acc[mt][nt][2] += c0; acc[mt][nt][3] += c1;
                }
            }
        }

        // ---- per tile: softmax, stage 2, scale, stage into consumed F rows ----
        #pragma unroll
        for (int mt = 0; mt < 2; mt++) {
            float mg = -1e30f, mg8 = -1e30f;
            #pragma unroll
            for (int nt = 0; nt < 8; nt++) {
                mg  = fmaxf(mg,  fmaxf(acc[mt][nt][0], acc[mt][nt][1]));
                mg8 = fmaxf(mg8, fmaxf(acc[mt][nt][2], acc[mt][nt][3]));
            }
            mg  = fmaxf(mg,  __shfl_xor_sync(0xffffffffu, mg, 1));
            mg  = fmaxf(mg,  __shfl_xor_sync(0xffffffffu, mg, 2));
            mg8 = fmaxf(mg8, __shfl_xor_sync(0xffffffffu, mg8, 1));
            mg8 = fmaxf(mg8, __shfl_xor_sync(0xffffffffu, mg8, 2));

            uint32_t pH[8][2];
            #pragma unroll
            for (int nt = 0; nt < 8; nt++) {
                const float p0 = ex2f(acc[mt][nt][0] - mg);
                const float p1 = ex2f(acc[mt][nt][1] - mg);
                const float p2 = ex2f(acc[mt][nt][2] - mg8);
                const float p3 = ex2f(acc[mt][nt][3] - mg8);
                pH[nt][0] = h2u(__floats2half2_rn(p0, p1));
                pH[nt][1] = h2u(__floats2half2_rn(p2, p3));
            }

            float acc2[3][4];
            #pragma unroll
            for (int nt = 0; nt < 3; nt++)
                #pragma unroll
                for (int i = 0; i < 4; i++) acc2[nt][i] = 0.0f;

            #pragma unroll
            for (int ks2 = 0; ks2 < 4; ks2++) {
                uint32_t bW2[3][2];
                {
                    uint32_t r[4];
                    ldsm4(r, w2b + nrowB * PF2B + ks2 * 32 + koffB);
                    bW2[0][0] = r[0]; bW2[0][1] = r[1];
                    bW2[1][0] = r[2]; bW2[1][1] = r[3];
                    uint32_t r2[2];
                    ldsm2(r2, w2b + (16 + (lane & 7)) * PF2B + ks2 * 32 + koffB);
                    bW2[2][0] = r2[0]; bW2[2][1] = r2[1];
                }
                const int nt2 = 2 * ks2;
                uint32_t a2[4];
                a2[0] = pH[nt2][0];   a2[1] = pH[nt2][1];
                a2[2] = pH[nt2+1][0]; a2[3] = pH[nt2+1][1];
                #pragma unroll
                for (int nt = 0; nt < 3; nt++)
                    mma16816(acc2[nt], a2, bW2[nt]);
            }

            const float likeg  = __shfl_sync(0xffffffffu, acc2[2][0], lane & ~3);
            const float likeg8 = __shfl_sync(0xffffffffu, acc2[2][2], lane & ~3);
            const float invg  = __fdividef(1.0f, likeg);
            const float invg8 = __fdividef(1.0f, likeg8);
            const int r = rowbase + mt * 16 + g;
            // stage into this warp's own consumed F rows (first 64 B of each row)
            fstg[r * PF1F + 2*t]         = acc2[0][0] * invg;
            fstg[r * PF1F + 2*t + 1]     = acc2[0][1] * invg;
            fstg[r * PF1F + 8 + 2*t]     = acc2[1][0] * invg;
            fstg[r * PF1F + 9 + 2*t]     = acc2[1][1] * invg;
            fstg[(r+8) * PF1F + 2*t]     = acc2[0][2] * invg8;
            fstg[(r+8) * PF1F + 2*t + 1] = acc2[0][3] * invg8;
            fstg[(r+8) * PF1F + 8 + 2*t] = acc2[1][2] * invg8;
            fstg[(r+8) * PF1F + 9 + 2*t] = acc2[1][3] * invg8;
            if (t == 0) {
                if (base + r < T)     llsum += __logf(likeg)  + mg  * LN2F;
                if (base + r + 8 < T) llsum += __logf(likeg8) + mg8 * LN2F;
            }
        }
    }

    // ---- block-wide coalesced copy-out ----
    __syncthreads();
    {
        float* op = out + 1 + (size_t)base * GMM_D;
        const int limit = min(PPB, T - base) * GMM_D;
        for (int i = tid; i < limit; i += TPB)
            op[i] = fstg[(i >> 4) * PF1F + (i & 15)];
    }

    // deterministic block reduction + fused finalize
    sRed[tid] = llsum;
    __syncthreads();
    #pragma unroll
    for (int s = TPB / 2; s > 0; s >>= 1) {
        if (tid < s) sRed[tid] += sRed[tid + s];
        __syncthreads();
    }
    if (tid == 0) {
        g_part[blockIdx.x] = sRed[0];
        __threadfence();
        unsigned old = atomicAdd(&g_count, 1u);
        sLast = (old == (unsigned)(gridDim.x - 1));
    }
    __syncthreads();
    if (sLast) {
        __threadfence();
        float acc3 = 0.0f;
        for (int i = tid; i < (int)gridDim.x; i += TPB) acc3 += g_part[i];
        sRed[tid] = acc3;
        __syncthreads();
        #pragma unroll
        for (int s = TPB / 2; s > 0; s >>= 1) {
            if (tid < s) sRed[tid] += sRed[tid + s];
            __syncthreads();
        }
        if (tid == 0) {
            out[0] = sRed[0] * invT;
            g_count = 0;
        }
    }
}

extern "C" void kernel_launch(void* const* d_in, const int* in_sizes, int n_in,
                              void* d_out, int out_size) {
    const float* data  = (const float*)d_in[0];
    const float* wghts = (const float*)d_in[1];
    const float* means = (const float*)d_in[2];
    const float* dcovs = (const float*)d_in[3];
    float* out = (float*)d_out;

    const int T = in_sizes[0] / GMM_D;
    const int grid = (T + PPB - 1) / PPB;

    gmm_precompute<<<1, 1024>>>(wghts, means, dcovs);
    cudaFuncSetAttribute(gmm_main, cudaFuncAttributeMaxDynamicSharedMemorySize, DSMEM);
    gmm_main<<<grid, TPB, DSMEM>>>(data, out, T, 1.0f / (float)T);
}